// round 8
// baseline (speedup 1.0000x reference)
#include <cuda_runtime.h>
#include <cstdint>

// ---------------------------------------------------------------------------
// DeepSeek MoE block: T=4096 tokens, D=2048, H=1408, E=8 experts, top-2.
//   out = x + sum_{k=0,1} w_k * ( silu(x W1[e_k]^T) * (x W3[e_k]^T) ) W2[e_k]^T
// R6: mma.sync TF32 path (tcgen05 unavailable: harness targets compute_103 base
//     ISA). Double-buffered smem, BK=32, one barrier per chunk, LDG prefetch
//     overlapped with the MMA phase.
// ---------------------------------------------------------------------------

#define DD 2048
#define HH 1408
#define EE 8
#define TT 4096
#define BM 128
#define BN 64
#define BK 32
#define MAXTILES 72                 // sum ceil(cnt_e/128) <= 8192/128 + 8
#define SLOTCAP (MAXTILES * BM)

#define NC_UP (DD / BK)             // 64 chunks
#define NC_DN (HH / BK)             // 44 chunks

// smem word-geometry: row stride 36 words (BK + 4 pad, conflict-free)
#define RS 36
#define A_WORDS   (BM * RS)                 // 4608
#define B_WORDS   (BN * RS)                 // 2304
#define STG_UP_W  (A_WORDS + 2 * B_WORDS)   // 9216 words
#define STG_DN_W  (A_WORDS + B_WORDS)       // 6912 words
#define SMEM_UP_B (2 * STG_UP_W * 4)        // 73728 bytes
#define SMEM_DN_B (2 * STG_DN_W * 4)        // 55296 bytes

// Static device scratch (allocation-free per harness rules)
__device__ float g_h[(size_t)SLOTCAP * HH];    // intermediate h (gate weight folded in)
__device__ float g_yp[(size_t)SLOTCAP * DD];   // per-pair down-proj outputs
__device__ int   g_ptok[SLOTCAP];
__device__ float g_pw[SLOTCAP];
__device__ int   g_counts[EE];
__device__ int   g_cursor[EE];
__device__ int   g_tile_e[MAXTILES];
__device__ int   g_topk_e[TT * 2];
__device__ float g_topk_w[TT * 2];
__device__ int   g_tokpair[TT * 2];

// Round-to-nearest TF32 (truncation would bias products ~5e-4)
__device__ __forceinline__ uint32_t f2tf(float f) {
    uint32_t u;
    asm("cvt.rna.tf32.f32 %0, %1;" : "=r"(u) : "f"(f));
    return u;
}

__device__ __forceinline__ void mma8(float* c, const uint32_t* a, uint32_t b0, uint32_t b1) {
    asm volatile(
        "mma.sync.aligned.m16n8k8.row.col.f32.tf32.tf32.f32 "
        "{%0,%1,%2,%3}, {%4,%5,%6,%7}, {%8,%9}, {%0,%1,%2,%3};\n"
        : "+f"(c[0]), "+f"(c[1]), "+f"(c[2]), "+f"(c[3])
        : "r"(a[0]), "r"(a[1]), "r"(a[2]), "r"(a[3]), "r"(b0), "r"(b1));
}

__device__ __forceinline__ void cvt_sts4(uint32_t* dst, float4 v) {
    uint4 u;
    u.x = f2tf(v.x); u.y = f2tf(v.y); u.z = f2tf(v.z); u.w = f2tf(v.w);
    *(uint4*)dst = u;
}

// ---------------------------------------------------------------------------
__global__ void k_init() {
    int i = blockIdx.x * blockDim.x + threadIdx.x;
    if (i < SLOTCAP) g_ptok[i] = -1;
    if (i < EE) g_counts[i] = 0;
}

// One warp per token: logits over 8 experts, softmax, top-2.
__global__ __launch_bounds__(256) void k_gate(const float* __restrict__ x,
                                              const float* __restrict__ Wg) {
    int w = (blockIdx.x * 256 + threadIdx.x) >> 5;
    int lane = threadIdx.x & 31;
    if (w >= TT) return;
    const float* xr = x + (size_t)w * DD;
    float acc[EE];
#pragma unroll
    for (int e = 0; e < EE; e++) acc[e] = 0.f;
    for (int k = lane; k < DD; k += 32) {
        float xv = xr[k];
#pragma unroll
        for (int e = 0; e < EE; e++) acc[e] += xv * Wg[e * DD + k];
    }
#pragma unroll
    for (int e = 0; e < EE; e++) {
#pragma unroll
        for (int off = 16; off; off >>= 1)
            acc[e] += __shfl_xor_sync(0xffffffffu, acc[e], off);
    }
    if (lane == 0) {
        float mx = acc[0];
#pragma unroll
        for (int e = 1; e < EE; e++) mx = fmaxf(mx, acc[e]);
        float ex[EE], sum = 0.f;
#pragma unroll
        for (int e = 0; e < EE; e++) { ex[e] = __expf(acc[e] - mx); sum += ex[e]; }
        float inv = 1.f / sum;
        int i0 = 0; float p0 = ex[0];
#pragma unroll
        for (int e = 1; e < EE; e++) if (ex[e] > p0) { p0 = ex[e]; i0 = e; }
        int i1 = -1; float p1 = -1.f;
#pragma unroll
        for (int e = 0; e < EE; e++)
            if (e != i0 && ex[e] > p1) { p1 = ex[e]; i1 = e; }
        g_topk_e[2 * w]     = i0; g_topk_w[2 * w]     = p0 * inv;
        g_topk_e[2 * w + 1] = i1; g_topk_w[2 * w + 1] = p1 * inv;
        atomicAdd(&g_counts[i0], 1);
        atomicAdd(&g_counts[i1], 1);
    }
}

// Tiny: 128-aligned segment starts + tile->expert map.
__global__ void k_plan() {
    if (threadIdx.x == 0) {
        int start = 0, nt = 0;
        for (int e = 0; e < EE; e++) {
            g_cursor[e] = start;
            int c = g_counts[e];
            int tiles = (c + BM - 1) / BM;
            for (int i = 0; i < tiles; i++) g_tile_e[nt++] = e;
            start += tiles * BM;
        }
        for (; nt < MAXTILES; nt++) g_tile_e[nt] = -1;
    }
}

__global__ void k_scatter() {
    int t = blockIdx.x * blockDim.x + threadIdx.x;
    if (t >= TT) return;
#pragma unroll
    for (int k = 0; k < 2; k++) {
        int e = g_topk_e[2 * t + k];
        float w = g_topk_w[2 * t + k];
        int slot = atomicAdd(&g_cursor[e], 1);
        g_ptok[slot] = t;
        g_pw[slot] = w;
        g_tokpair[2 * t + k] = slot;
    }
}

// ---------------------------------------------------------------------------
// GEMM1: per m-tile (single expert), U = x W1^T, V = x W3^T over K=D,
// epilogue h = w * silu(U) * V.  128x64x32 chunks, double-buffered smem,
// 8 warps (4x2), each warp 32x32, one __syncthreads per chunk.
__global__ __launch_bounds__(256, 1) void k_up(const float* __restrict__ x,
                                               const float* __restrict__ W1,
                                               const float* __restrict__ W3) {
    int tile = blockIdx.y;
    int e = g_tile_e[tile];
    if (e < 0) return;
    int nb = blockIdx.x * BN;
    int slot0 = tile * BM;

    extern __shared__ uint32_t sm[];   // [2][STG_UP_W]: A | B1 | B3

    int tid = threadIdx.x, lane = tid & 31, wid = tid >> 5;
    int wm = (wid & 3) * 32, wn = (wid >> 2) * 32;
    int g = lane >> 2, t4 = lane & 3;

    // ---- staging geometry: 256 threads stage A=1024 float4, B1/B3=512 each
    // A float4 i (i=0..3): id = tid + 256*i -> row = id>>3 (0..127), c4 = id&7
    const float* aP[4]; uint32_t aO[4];
#pragma unroll
    for (int i = 0; i < 4; i++) {
        int id = tid + 256 * i;
        int row = id >> 3, c4 = id & 7;
        int tok = g_ptok[slot0 + row]; if (tok < 0) tok = 0;
        aP[i] = x + (size_t)tok * DD + c4 * 4;
        aO[i] = row * RS + c4 * 4;
    }
    // B float4 j (j=0..1): id = tid + 256*j -> row = id>>3 (0..63), c4 = id&7
    const float *b1P[2], *b3P[2]; uint32_t bO[2];
#pragma unroll
    for (int j = 0; j < 2; j++) {
        int id = tid + 256 * j;
        int row = id >> 3, c4 = id & 7;
        size_t ro = ((size_t)e * HH + nb + row) * DD + c4 * 4;
        b1P[j] = W1 + ro;
        b3P[j] = W3 + ro;
        bO[j] = row * RS + c4 * 4;
    }

    float acc_u[2][4][4], acc_v[2][4][4];
#pragma unroll
    for (int mi = 0; mi < 2; mi++)
#pragma unroll
        for (int ni = 0; ni < 4; ni++)
#pragma unroll
            for (int q = 0; q < 4; q++) { acc_u[mi][ni][q] = 0.f; acc_v[mi][ni][q] = 0.f; }

    // ---- prologue: stage chunk 0 into buffer 0
    {
        uint32_t* A0 = sm;
        uint32_t* B10 = sm + A_WORDS;
        uint32_t* B30 = sm + A_WORDS + B_WORDS;
#pragma unroll
        for (int i = 0; i < 4; i++) cvt_sts4(&A0[aO[i]], *(const float4*)aP[i]);
#pragma unroll
        for (int j = 0; j < 2; j++) {
            cvt_sts4(&B10[bO[j]], *(const float4*)b1P[j]);
            cvt_sts4(&B30[bO[j]], *(const float4*)b3P[j]);
        }
    }
    __syncthreads();

#pragma unroll 1
    for (int c = 0; c < NC_UP; c++) {
        int s = c & 1;
        uint32_t* As  = sm + s * STG_UP_W;
        uint32_t* B1s = As + A_WORDS;
        uint32_t* B3s = As + A_WORDS + B_WORDS;

        // prefetch next chunk from gmem (latency hidden under MMAs below)
        float4 pa0, pa1, pa2, pa3, p10, p11, p30, p31;
        int kn = (c + 1) * BK;
        if (c + 1 < NC_UP) {
            pa0 = *(const float4*)(aP[0] + kn);
            pa1 = *(const float4*)(aP[1] + kn);
            pa2 = *(const float4*)(aP[2] + kn);
            pa3 = *(const float4*)(aP[3] + kn);
            p10 = *(const float4*)(b1P[0] + kn);
            p11 = *(const float4*)(b1P[1] + kn);
            p30 = *(const float4*)(b3P[0] + kn);
            p31 = *(const float4*)(b3P[1] + kn);
        }

        // MMA phase: 4 k8-steps over the 32-wide chunk
#pragma unroll
        for (int h = 0; h < 4; h++) {
            uint32_t a[2][4];
#pragma unroll
            for (int mi = 0; mi < 2; mi++) {
                int r = wm + mi * 16 + g;
                a[mi][0] = As[r * RS + h * 8 + t4];
                a[mi][1] = As[(r + 8) * RS + h * 8 + t4];
                a[mi][2] = As[r * RS + h * 8 + t4 + 4];
                a[mi][3] = As[(r + 8) * RS + h * 8 + t4 + 4];
            }
#pragma unroll
            for (int ni = 0; ni < 4; ni++) {
                int rn = wn + ni * 8 + g;
                uint32_t bu0 = B1s[rn * RS + h * 8 + t4], bu1 = B1s[rn * RS + h * 8 + t4 + 4];
                uint32_t bv0 = B3s[rn * RS + h * 8 + t4], bv1 = B3s[rn * RS + h * 8 + t4 + 4];
#pragma unroll
                for (int mi = 0; mi < 2; mi++) {
                    mma8(acc_u[mi][ni], a[mi], bu0, bu1);
                    mma8(acc_v[mi][ni], a[mi], bv0, bv1);
                }
            }
        }

        // write prefetched chunk into the other buffer
        if (c + 1 < NC_UP) {
            uint32_t* An  = sm + (s ^ 1) * STG_UP_W;
            uint32_t* B1n = An + A_WORDS;
            uint32_t* B3n = An + A_WORDS + B_WORDS;
            cvt_sts4(&An[aO[0]], pa0);
            cvt_sts4(&An[aO[1]], pa1);
            cvt_sts4(&An[aO[2]], pa2);
            cvt_sts4(&An[aO[3]], pa3);
            cvt_sts4(&B1n[bO[0]], p10);
            cvt_sts4(&B1n[bO[1]], p11);
            cvt_sts4(&B3n[bO[0]], p30);
            cvt_sts4(&B3n[bO[1]], p31);
        }
        __syncthreads();
    }

    // epilogue: h = w * silu(u) * v
#pragma unroll
    for (int mi = 0; mi < 2; mi++) {
#pragma unroll
        for (int r = 0; r < 2; r++) {
            int m = wm + mi * 16 + r * 8 + g;
            int slot = slot0 + m;
            int tok = g_ptok[slot];
            if (tok < 0) continue;
            float w = g_pw[slot];
            float* hrow = g_h + (size_t)slot * HH + nb + wn;
#pragma unroll
            for (int ni = 0; ni < 4; ni++) {
#pragma unroll
                for (int cc = 0; cc < 2; cc++) {
                    float uu = acc_u[mi][ni][r * 2 + cc];
                    float vv = acc_v[mi][ni][r * 2 + cc];
                    float si = uu / (1.f + __expf(-uu));
                    hrow[ni * 8 + t4 * 2 + cc] = w * si * vv;
                }
            }
        }
    }
}

// ---------------------------------------------------------------------------
// GEMM2: y_pair = h W2^T over K=H. Same structure, single B matrix.
__global__ __launch_bounds__(256, 1) void k_down(const float* __restrict__ W2) {
    int tile = blockIdx.y;
    int e = g_tile_e[tile];
    if (e < 0) return;
    int nb = blockIdx.x * BN;
    int slot0 = tile * BM;

    extern __shared__ uint32_t sm[];   // [2][STG_DN_W]: A | B

    int tid = threadIdx.x, lane = tid & 31, wid = tid >> 5;
    int wm = (wid & 3) * 32, wn = (wid >> 2) * 32;
    int g = lane >> 2, t4 = lane & 3;

    const float* aP[4]; uint32_t aO[4];
#pragma unroll
    for (int i = 0; i < 4; i++) {
        int id = tid + 256 * i;
        int row = id >> 3, c4 = id & 7;
        aP[i] = g_h + (size_t)(slot0 + row) * HH + c4 * 4;
        aO[i] = row * RS + c4 * 4;
    }
    const float* bP[2]; uint32_t bO[2];
#pragma unroll
    for (int j = 0; j < 2; j++) {
        int id = tid + 256 * j;
        int row = id >> 3, c4 = id & 7;
        bP[j] = W2 + ((size_t)e * DD + nb + row) * HH + c4 * 4;
        bO[j] = row * RS + c4 * 4;
    }

    float acc[2][4][4];
#pragma unroll
    for (int mi = 0; mi < 2; mi++)
#pragma unroll
        for (int ni = 0; ni < 4; ni++)
#pragma unroll
            for (int q = 0; q < 4; q++) acc[mi][ni][q] = 0.f;

    {   // prologue: chunk 0 -> buffer 0
        uint32_t* A0 = sm;
        uint32_t* B0 = sm + A_WORDS;
#pragma unroll
        for (int i = 0; i < 4; i++) cvt_sts4(&A0[aO[i]], *(const float4*)aP[i]);
#pragma unroll
        for (int j = 0; j < 2; j++) cvt_sts4(&B0[bO[j]], *(const float4*)bP[j]);
    }
    __syncthreads();

#pragma unroll 1
    for (int c = 0; c < NC_DN; c++) {
        int s = c & 1;
        uint32_t* As = sm + s * STG_DN_W;
        uint32_t* Bs = As + A_WORDS;

        float4 pa0, pa1, pa2, pa3, pb0, pb1;
        int kn = (c + 1) * BK;
        if (c + 1 < NC_DN) {
            pa0 = *(const float4*)(aP[0] + kn);
            pa1 = *(const float4*)(aP[1] + kn);
            pa2 = *(const float4*)(aP[2] + kn);
            pa3 = *(const float4*)(aP[3] + kn);
            pb0 = *(const float4*)(bP[0] + kn);
            pb1 = *(const float4*)(bP[1] + kn);
        }

#pragma unroll
        for (int h = 0; h < 4; h++) {
            uint32_t a[2][4];
#pragma unroll
            for (int mi = 0; mi < 2; mi++) {
                int r = wm + mi * 16 + g;
                a[mi][0] = As[r * RS + h * 8 + t4];
                a[mi][1] = As[(r + 8) * RS + h * 8 + t4];
                a[mi][2] = As[r * RS + h * 8 + t4 + 4];
                a[mi][3] = As[(r + 8) * RS + h * 8 + t4 + 4];
            }
#pragma unroll
            for (int ni = 0; ni < 4; ni++) {
                int rn = wn + ni * 8 + g;
                uint32_t b0 = Bs[rn * RS + h * 8 + t4], b1 = Bs[rn * RS + h * 8 + t4 + 4];
#pragma unroll
                for (int mi = 0; mi < 2; mi++) mma8(acc[mi][ni], a[mi], b0, b1);
            }
        }

        if (c + 1 < NC_DN) {
            uint32_t* An = sm + (s ^ 1) * STG_DN_W;
            uint32_t* Bn = An + A_WORDS;
            cvt_sts4(&An[aO[0]], pa0);
            cvt_sts4(&An[aO[1]], pa1);
            cvt_sts4(&An[aO[2]], pa2);
            cvt_sts4(&An[aO[3]], pa3);
            cvt_sts4(&Bn[bO[0]], pb0);
            cvt_sts4(&Bn[bO[1]], pb1);
        }
        __syncthreads();
    }

#pragma unroll
    for (int mi = 0; mi < 2; mi++) {
#pragma unroll
        for (int r = 0; r < 2; r++) {
            int m = wm + mi * 16 + r * 8 + g;
            int slot = slot0 + m;
            if (g_ptok[slot] < 0) continue;
            float* yrow = g_yp + (size_t)slot * DD + nb + wn;
#pragma unroll
            for (int ni = 0; ni < 4; ni++) {
#pragma unroll
                for (int cc = 0; cc < 2; cc++)
                    yrow[ni * 8 + t4 * 2 + cc] = acc[mi][ni][r * 2 + cc];
            }
        }
    }
}

// out[t] = x[t] + y_pair[p0(t)] + y_pair[p1(t)]  (deterministic gather)
__global__ __launch_bounds__(512) void k_combine(const float* __restrict__ x,
                                                 float* __restrict__ out) {
    int t = blockIdx.x;
    int d = threadIdx.x * 4;
    int s0 = g_tokpair[2 * t], s1 = g_tokpair[2 * t + 1];
    float4 xv = *(const float4*)(x + (size_t)t * DD + d);
    float4 a = *(const float4*)(g_yp + (size_t)s0 * DD + d);
    float4 b = *(const float4*)(g_yp + (size_t)s1 * DD + d);
    float4 o;
    o.x = xv.x + a.x + b.x;
    o.y = xv.y + a.y + b.y;
    o.z = xv.z + a.z + b.z;
    o.w = xv.w + a.w + b.w;
    *(float4*)(out + (size_t)t * DD + d) = o;
}

// ---------------------------------------------------------------------------
extern "C" void kernel_launch(void* const* d_in, const int* in_sizes, int n_in,
                              void* d_out, int out_size) {
    const float* x  = (const float*)d_in[0];
    const float* Wg = (const float*)d_in[1];
    const float* W1 = (const float*)d_in[2];
    const float* W3 = (const float*)d_in[3];
    const float* W2 = (const float*)d_in[4];
    float* out = (float*)d_out;

    static int smem_set = 0;
    if (!smem_set) {
        cudaFuncSetAttribute(k_up,   cudaFuncAttributeMaxDynamicSharedMemorySize, SMEM_UP_B);
        cudaFuncSetAttribute(k_down, cudaFuncAttributeMaxDynamicSharedMemorySize, SMEM_DN_B);
        smem_set = 1;
    }

    k_init<<<(SLOTCAP + 255) / 256, 256>>>();
    k_gate<<<(TT * 32 + 255) / 256, 256>>>(x, Wg);
    k_plan<<<1, 32>>>();
    k_scatter<<<(TT + 255) / 256, 256>>>();
    k_up<<<dim3(HH / BN, MAXTILES), 256, SMEM_UP_B>>>(x, W1, W3);
    k_down<<<dim3(DD / BN, MAXTILES), 256, SMEM_DN_B>>>(W2);
    k_combine<<<TT, DD / 4>>>(x, out);
}

// round 11
// speedup vs baseline: 1.4607x; 1.4607x over previous
#include <cuda_runtime.h>
#include <cstdint>

// ---------------------------------------------------------------------------
// DeepSeek MoE block: T=4096 tokens, D=2048, H=1408, E=8 experts, top-2.
//   out = x + sum_{k=0,1} w_k * ( silu(x W1[e_k]^T) * (x W3[e_k]^T) ) W2[e_k]^T
// R9: fp16 mma.sync m16n8k16 (same 10-bit mantissa as TF32, 2x K per instr).
//     tcgen05 unavailable (harness targets compute_103 base ISA).
//     Double-buffered smem, BK=32, one barrier per chunk, LDG prefetch.
// ---------------------------------------------------------------------------

#define DD 2048
#define HH 1408
#define EE 8
#define TT 4096
#define BM 128
#define BN 64
#define BK 32
#define MAXTILES 72                 // sum ceil(cnt_e/128) <= 8192/128 + 8
#define SLOTCAP (MAXTILES * BM)

#define NC_UP (DD / BK)             // 64 chunks
#define NC_DN (HH / BK)             // 44 chunks

// smem geometry (u32 units): 16 f16x2 words per row + 4 pad (conflict-free)
#define RS 20
#define A_WORDS   (BM * RS)                 // 2560
#define B_WORDS   (BN * RS)                 // 1280
#define STG_UP_W  (A_WORDS + 2 * B_WORDS)   // 5120 words
#define STG_DN_W  (A_WORDS + B_WORDS)       // 3840 words
#define SMEM_UP_B (2 * STG_UP_W * 4)        // 40960 bytes (< 48KB default)
#define SMEM_DN_B (2 * STG_DN_W * 4)        // 30720 bytes

// Static device scratch (allocation-free per harness rules)
__device__ float g_h[(size_t)SLOTCAP * HH];    // intermediate h (gate weight folded in)
__device__ float g_yp[(size_t)SLOTCAP * DD];   // per-pair down-proj outputs
__device__ int   g_ptok[SLOTCAP];
__device__ float g_pw[SLOTCAP];
__device__ int   g_counts[EE];
__device__ int   g_cursor[EE];
__device__ int   g_tile_e[MAXTILES];
__device__ int   g_topk_e[TT * 2];
__device__ float g_topk_w[TT * 2];
__device__ int   g_tokpair[TT * 2];

// pack two fp32 -> f16x2 (round-to-nearest; upper = first operand)
__device__ __forceinline__ uint32_t pack_h2(float hi, float lo) {
    uint32_t r;
    asm("cvt.rn.f16x2.f32 %0, %1, %2;" : "=r"(r) : "f"(hi), "f"(lo));
    return r;
}
__device__ __forceinline__ void cvt_sts_h4(uint32_t* dst, float4 v) {
    uint2 u;
    u.x = pack_h2(v.y, v.x);    // lo half = smaller k
    u.y = pack_h2(v.w, v.z);
    *(uint2*)dst = u;
}

__device__ __forceinline__ void mma16(float* c, const uint32_t* a, uint32_t b0, uint32_t b1) {
    asm volatile(
        "mma.sync.aligned.m16n8k16.row.col.f32.f16.f16.f32 "
        "{%0,%1,%2,%3}, {%4,%5,%6,%7}, {%8,%9}, {%0,%1,%2,%3};\n"
        : "+f"(c[0]), "+f"(c[1]), "+f"(c[2]), "+f"(c[3])
        : "r"(a[0]), "r"(a[1]), "r"(a[2]), "r"(a[3]), "r"(b0), "r"(b1));
}

// ---------------------------------------------------------------------------
__global__ void k_init() {
    int i = blockIdx.x * blockDim.x + threadIdx.x;
    if (i < SLOTCAP) g_ptok[i] = -1;
    if (i < EE) g_counts[i] = 0;
}

// One warp per token: logits over 8 experts, softmax, top-2.
__global__ __launch_bounds__(256) void k_gate(const float* __restrict__ x,
                                              const float* __restrict__ Wg) {
    int w = (blockIdx.x * 256 + threadIdx.x) >> 5;
    int lane = threadIdx.x & 31;
    if (w >= TT) return;
    const float* xr = x + (size_t)w * DD;
    float acc[EE];
#pragma unroll
    for (int e = 0; e < EE; e++) acc[e] = 0.f;
    for (int k = lane; k < DD; k += 32) {
        float xv = xr[k];
#pragma unroll
        for (int e = 0; e < EE; e++) acc[e] += xv * Wg[e * DD + k];
    }
#pragma unroll
    for (int e = 0; e < EE; e++) {
#pragma unroll
        for (int off = 16; off; off >>= 1)
            acc[e] += __shfl_xor_sync(0xffffffffu, acc[e], off);
    }
    if (lane == 0) {
        float mx = acc[0];
#pragma unroll
        for (int e = 1; e < EE; e++) mx = fmaxf(mx, acc[e]);
        float ex[EE], sum = 0.f;
#pragma unroll
        for (int e = 0; e < EE; e++) { ex[e] = __expf(acc[e] - mx); sum += ex[e]; }
        float inv = 1.f / sum;
        int i0 = 0; float p0 = ex[0];
#pragma unroll
        for (int e = 1; e < EE; e++) if (ex[e] > p0) { p0 = ex[e]; i0 = e; }
        int i1 = -1; float p1 = -1.f;
#pragma unroll
        for (int e = 0; e < EE; e++)
            if (e != i0 && ex[e] > p1) { p1 = ex[e]; i1 = e; }
        g_topk_e[2 * w]     = i0; g_topk_w[2 * w]     = p0 * inv;
        g_topk_e[2 * w + 1] = i1; g_topk_w[2 * w + 1] = p1 * inv;
        atomicAdd(&g_counts[i0], 1);
        atomicAdd(&g_counts[i1], 1);
    }
}

// Tiny: 128-aligned segment starts + tile->expert map.
__global__ void k_plan() {
    if (threadIdx.x == 0) {
        int start = 0, nt = 0;
        for (int e = 0; e < EE; e++) {
            g_cursor[e] = start;
            int c = g_counts[e];
            int tiles = (c + BM - 1) / BM;
            for (int i = 0; i < tiles; i++) g_tile_e[nt++] = e;
            start += tiles * BM;
        }
        for (; nt < MAXTILES; nt++) g_tile_e[nt] = -1;
    }
}

__global__ void k_scatter() {
    int t = blockIdx.x * blockDim.x + threadIdx.x;
    if (t >= TT) return;
#pragma unroll
    for (int k = 0; k < 2; k++) {
        int e = g_topk_e[2 * t + k];
        float w = g_topk_w[2 * t + k];
        int slot = atomicAdd(&g_cursor[e], 1);
        g_ptok[slot] = t;
        g_pw[slot] = w;
        g_tokpair[2 * t + k] = slot;
    }
}

// ---------------------------------------------------------------------------
// GEMM1: per m-tile (single expert), U = x W1^T, V = x W3^T over K=D,
// epilogue h = w * silu(U) * V.  128x64x32 chunks (2 x k16 mma steps),
// double-buffered smem, 8 warps (4x2), each warp 32x32.
__global__ __launch_bounds__(256, 1) void k_up(const float* __restrict__ x,
                                               const float* __restrict__ W1,
                                               const float* __restrict__ W3) {
    int tile = blockIdx.y;
    int e = g_tile_e[tile];
    if (e < 0) return;
    int nb = blockIdx.x * BN;
    int slot0 = tile * BM;

    extern __shared__ uint32_t sm[];   // [2][STG_UP_W]: A | B1 | B3  (f16x2 words)

    int tid = threadIdx.x, lane = tid & 31, wid = tid >> 5;
    int wm = (wid & 3) * 32, wn = (wid >> 2) * 32;
    int g = lane >> 2, t4 = lane & 3;

    // staging: A = 1024 uint2 (4/thread), B1/B3 = 512 uint2 (2/thread each)
    // uint2 i: row = i>>3 (8 uint2/row of 4 k-elems each), c2 = i&7
    const float* aP[4]; uint32_t aO[4];
#pragma unroll
    for (int i = 0; i < 4; i++) {
        int id = tid + 256 * i;
        int row = id >> 3, c2 = id & 7;
        int tok = g_ptok[slot0 + row]; if (tok < 0) tok = 0;
        aP[i] = x + (size_t)tok * DD + c2 * 4;
        aO[i] = row * RS + c2 * 2;
    }
    const float *b1P[2], *b3P[2]; uint32_t bO[2];
#pragma unroll
    for (int j = 0; j < 2; j++) {
        int id = tid + 256 * j;
        int row = id >> 3, c2 = id & 7;
        size_t ro = ((size_t)e * HH + nb + row) * DD + c2 * 4;
        b1P[j] = W1 + ro;
        b3P[j] = W3 + ro;
        bO[j] = row * RS + c2 * 2;
    }

    float acc_u[2][4][4], acc_v[2][4][4];
#pragma unroll
    for (int mi = 0; mi < 2; mi++)
#pragma unroll
        for (int ni = 0; ni < 4; ni++)
#pragma unroll
            for (int q = 0; q < 4; q++) { acc_u[mi][ni][q] = 0.f; acc_v[mi][ni][q] = 0.f; }

    // prologue: stage chunk 0 into buffer 0
    {
        uint32_t* A0  = sm;
        uint32_t* B10 = sm + A_WORDS;
        uint32_t* B30 = sm + A_WORDS + B_WORDS;
#pragma unroll
        for (int i = 0; i < 4; i++) cvt_sts_h4(&A0[aO[i]], *(const float4*)aP[i]);
#pragma unroll
        for (int j = 0; j < 2; j++) {
            cvt_sts_h4(&B10[bO[j]], *(const float4*)b1P[j]);
            cvt_sts_h4(&B30[bO[j]], *(const float4*)b3P[j]);
        }
    }
    __syncthreads();

#pragma unroll 1
    for (int c = 0; c < NC_UP; c++) {
        int s = c & 1;
        uint32_t* As  = sm + s * STG_UP_W;
        uint32_t* B1s = As + A_WORDS;
        uint32_t* B3s = As + A_WORDS + B_WORDS;

        // prefetch next chunk from gmem (hidden under MMAs below)
        float4 pa0, pa1, pa2, pa3, p10, p11, p30, p31;
        int kn = (c + 1) * BK;
        if (c + 1 < NC_UP) {
            pa0 = *(const float4*)(aP[0] + kn);
            pa1 = *(const float4*)(aP[1] + kn);
            pa2 = *(const float4*)(aP[2] + kn);
            pa3 = *(const float4*)(aP[3] + kn);
            p10 = *(const float4*)(b1P[0] + kn);
            p11 = *(const float4*)(b1P[1] + kn);
            p30 = *(const float4*)(b3P[0] + kn);
            p31 = *(const float4*)(b3P[1] + kn);
        }

        // MMA phase: 2 k16-steps over the 32-wide chunk
#pragma unroll
        for (int h = 0; h < 2; h++) {
            int h8 = h * 8;
            uint32_t a[2][4];
#pragma unroll
            for (int mi = 0; mi < 2; mi++) {
                int r = wm + mi * 16 + g;
                a[mi][0] = As[r * RS + h8 + t4];
                a[mi][1] = As[(r + 8) * RS + h8 + t4];
                a[mi][2] = As[r * RS + h8 + t4 + 4];
                a[mi][3] = As[(r + 8) * RS + h8 + t4 + 4];
            }
#pragma unroll
            for (int ni = 0; ni < 4; ni++) {
                int rn = wn + ni * 8 + g;
                uint32_t bu0 = B1s[rn * RS + h8 + t4], bu1 = B1s[rn * RS + h8 + t4 + 4];
                uint32_t bv0 = B3s[rn * RS + h8 + t4], bv1 = B3s[rn * RS + h8 + t4 + 4];
#pragma unroll
                for (int mi = 0; mi < 2; mi++) {
                    mma16(acc_u[mi][ni], a[mi], bu0, bu1);
                    mma16(acc_v[mi][ni], a[mi], bv0, bv1);
                }
            }
        }

        // write prefetched chunk into the other buffer
        if (c + 1 < NC_UP) {
            uint32_t* An  = sm + (s ^ 1) * STG_UP_W;
            uint32_t* B1n = An + A_WORDS;
            uint32_t* B3n = An + A_WORDS + B_WORDS;
            cvt_sts_h4(&An[aO[0]], pa0);
            cvt_sts_h4(&An[aO[1]], pa1);
            cvt_sts_h4(&An[aO[2]], pa2);
            cvt_sts_h4(&An[aO[3]], pa3);
            cvt_sts_h4(&B1n[bO[0]], p10);
            cvt_sts_h4(&B1n[bO[1]], p11);
            cvt_sts_h4(&B3n[bO[0]], p30);
            cvt_sts_h4(&B3n[bO[1]], p31);
        }
        __syncthreads();
    }

    // epilogue: h = w * silu(u) * v
#pragma unroll
    for (int mi = 0; mi < 2; mi++) {
#pragma unroll
        for (int r = 0; r < 2; r++) {
            int m = wm + mi * 16 + r * 8 + g;
            int slot = slot0 + m;
            int tok = g_ptok[slot];
            if (tok < 0) continue;
            float w = g_pw[slot];
            float* hrow = g_h + (size_t)slot * HH + nb + wn;
#pragma unroll
            for (int ni = 0; ni < 4; ni++) {
#pragma unroll
                for (int cc = 0; cc < 2; cc++) {
                    float uu = acc_u[mi][ni][r * 2 + cc];
                    float vv = acc_v[mi][ni][r * 2 + cc];
                    float si = uu / (1.f + __expf(-uu));
                    hrow[ni * 8 + t4 * 2 + cc] = w * si * vv;
                }
            }
        }
    }
}

// ---------------------------------------------------------------------------
// GEMM2: y_pair = h W2^T over K=H. Same structure, single B matrix.
__global__ __launch_bounds__(256, 1) void k_down(const float* __restrict__ W2) {
    int tile = blockIdx.y;
    int e = g_tile_e[tile];
    if (e < 0) return;
    int nb = blockIdx.x * BN;
    int slot0 = tile * BM;

    extern __shared__ uint32_t sm[];   // [2][STG_DN_W]: A | B

    int tid = threadIdx.x, lane = tid & 31, wid = tid >> 5;
    int wm = (wid & 3) * 32, wn = (wid >> 2) * 32;
    int g = lane >> 2, t4 = lane & 3;

    const float* aP[4]; uint32_t aO[4];
#pragma unroll
    for (int i = 0; i < 4; i++) {
        int id = tid + 256 * i;
        int row = id >> 3, c2 = id & 7;
        aP[i] = g_h + (size_t)(slot0 + row) * HH + c2 * 4;
        aO[i] = row * RS + c2 * 2;
    }
    const float* bP[2]; uint32_t bO[2];
#pragma unroll
    for (int j = 0; j < 2; j++) {
        int id = tid + 256 * j;
        int row = id >> 3, c2 = id & 7;
        bP[j] = W2 + ((size_t)e * DD + nb + row) * HH + c2 * 4;
        bO[j] = row * RS + c2 * 2;
    }

    float acc[2][4][4];
#pragma unroll
    for (int mi = 0; mi < 2; mi++)
#pragma unroll
        for (int ni = 0; ni < 4; ni++)
#pragma unroll
            for (int q = 0; q < 4; q++) acc[mi][ni][q] = 0.f;

    {   // prologue: chunk 0 -> buffer 0
        uint32_t* A0 = sm;
        uint32_t* B0 = sm + A_WORDS;
#pragma unroll
        for (int i = 0; i < 4; i++) cvt_sts_h4(&A0[aO[i]], *(const float4*)aP[i]);
#pragma unroll
        for (int j = 0; j < 2; j++) cvt_sts_h4(&B0[bO[j]], *(const float4*)bP[j]);
    }
    __syncthreads();

#pragma unroll 1
    for (int c = 0; c < NC_DN; c++) {
        int s = c & 1;
        uint32_t* As = sm + s * STG_DN_W;
        uint32_t* Bs = As + A_WORDS;

        float4 pa0, pa1, pa2, pa3, pb0, pb1;
        int kn = (c + 1) * BK;
        if (c + 1 < NC_DN) {
            pa0 = *(const float4*)(aP[0] + kn);
            pa1 = *(const float4*)(aP[1] + kn);
            pa2 = *(const float4*)(aP[2] + kn);
            pa3 = *(const float4*)(aP[3] + kn);
            pb0 = *(const float4*)(bP[0] + kn);
            pb1 = *(const float4*)(bP[1] + kn);
        }

#pragma unroll
        for (int h = 0; h < 2; h++) {
            int h8 = h * 8;
            uint32_t a[2][4];
#pragma unroll
            for (int mi = 0; mi < 2; mi++) {
                int r = wm + mi * 16 + g;
                a[mi][0] = As[r * RS + h8 + t4];
                a[mi][1] = As[(r + 8) * RS + h8 + t4];
                a[mi][2] = As[r * RS + h8 + t4 + 4];
                a[mi][3] = As[(r + 8) * RS + h8 + t4 + 4];
            }
#pragma unroll
            for (int ni = 0; ni < 4; ni++) {
                int rn = wn + ni * 8 + g;
                uint32_t b0 = Bs[rn * RS + h8 + t4], b1 = Bs[rn * RS + h8 + t4 + 4];
#pragma unroll
                for (int mi = 0; mi < 2; mi++) mma16(acc[mi][ni], a[mi], b0, b1);
            }
        }

        if (c + 1 < NC_DN) {
            uint32_t* An = sm + (s ^ 1) * STG_DN_W;
            uint32_t* Bn = An + A_WORDS;
            cvt_sts_h4(&An[aO[0]], pa0);
            cvt_sts_h4(&An[aO[1]], pa1);
            cvt_sts_h4(&An[aO[2]], pa2);
            cvt_sts_h4(&An[aO[3]], pa3);
            cvt_sts_h4(&Bn[bO[0]], pb0);
            cvt_sts_h4(&Bn[bO[1]], pb1);
        }
        __syncthreads();
    }

#pragma unroll
    for (int mi = 0; mi < 2; mi++) {
#pragma unroll
        for (int r = 0; r < 2; r++) {
            int m = wm + mi * 16 + r * 8 + g;
            int slot = slot0 + m;
            if (g_ptok[slot] < 0) continue;
            float* yrow = g_yp + (size_t)slot * DD + nb + wn;
#pragma unroll
            for (int ni = 0; ni < 4; ni++) {
#pragma unroll
                for (int cc = 0; cc < 2; cc++)
                    yrow[ni * 8 + t4 * 2 + cc] = acc[mi][ni][r * 2 + cc];
            }
        }
    }
}

// out[t] = x[t] + y_pair[p0(t)] + y_pair[p1(t)]  (deterministic gather)
__global__ __launch_bounds__(512) void k_combine(const float* __restrict__ x,
                                                 float* __restrict__ out) {
    int t = blockIdx.x;
    int d = threadIdx.x * 4;
    int s0 = g_tokpair[2 * t], s1 = g_tokpair[2 * t + 1];
    float4 xv = *(const float4*)(x + (size_t)t * DD + d);
    float4 a = *(const float4*)(g_yp + (size_t)s0 * DD + d);
    float4 b = *(const float4*)(g_yp + (size_t)s1 * DD + d);
    float4 o;
    o.x = xv.x + a.x + b.x;
    o.y = xv.y + a.y + b.y;
    o.z = xv.z + a.z + b.z;
    o.w = xv.w + a.w + b.w;
    *(float4*)(out + (size_t)t * DD + d) = o;
}

// ---------------------------------------------------------------------------
extern "C" void kernel_launch(void* const* d_in, const int* in_sizes, int n_in,
                              void* d_out, int out_size) {
    const float* x  = (const float*)d_in[0];
    const float* Wg = (const float*)d_in[1];
    const float* W1 = (const float*)d_in[2];
    const float* W3 = (const float*)d_in[3];
    const float* W2 = (const float*)d_in[4];
    float* out = (float*)d_out;

    // dynamic smem now fits the 48KB default: no attribute calls needed
    k_init<<<(SLOTCAP + 255) / 256, 256>>>();
    k_gate<<<(TT * 32 + 255) / 256, 256>>>(x, Wg);
    k_plan<<<1, 32>>>();
    k_scatter<<<(TT + 255) / 256, 256>>>();
    k_up<<<dim3(HH / BN, MAXTILES), 256, SMEM_UP_B>>>(x, W1, W3);
    k_down<<<dim3(DD / BN, MAXTILES), 256, SMEM_DN_B>>>(W2);
    k_combine<<<TT, DD / 4>>>(x, out);
}

// round 16
// speedup vs baseline: 1.5357x; 1.0513x over previous
#include <cuda_runtime.h>
#include <cstdint>

// ---------------------------------------------------------------------------
// DeepSeek MoE block: T=4096 tokens, D=2048, H=1408, E=8 experts, top-2.
//   out = x + sum_{k=0,1} w_k * ( silu(x W1[e_k]^T) * (x W3[e_k]^T) ) W2[e_k]^T
// R11: fp16 mma.sync m16n8k16; occupancy experiment — drop register prefetch
//      (R8 proved overlap neutral), cap regs via __launch_bounds__(256,2) so
//      2 CTAs/SM (4 warps/SMSP) can hide HMMA/LDS latency if exposed.
// ---------------------------------------------------------------------------

#define DD 2048
#define HH 1408
#define EE 8
#define TT 4096
#define BM 128
#define BN 64
#define BK 32
#define MAXTILES 72                 // sum ceil(cnt_e/128) <= 8192/128 + 8
#define SLOTCAP (MAXTILES * BM)

#define NC_UP (DD / BK)             // 64 chunks
#define NC_DN (HH / BK)             // 44 chunks

// smem geometry (u32 units): 16 f16x2 words per row + 4 pad (conflict-free)
#define RS 20
#define A_WORDS   (BM * RS)                 // 2560
#define B_WORDS   (BN * RS)                 // 1280
#define STG_UP_W  (A_WORDS + 2 * B_WORDS)   // 5120 words
#define STG_DN_W  (A_WORDS + B_WORDS)       // 3840 words
#define SMEM_UP_B (2 * STG_UP_W * 4)        // 40960 bytes (< 48KB default)
#define SMEM_DN_B (2 * STG_DN_W * 4)        // 30720 bytes

// Static device scratch (allocation-free per harness rules)
__device__ float g_h[(size_t)SLOTCAP * HH];    // intermediate h (gate weight folded in)
__device__ float g_yp[(size_t)SLOTCAP * DD];   // per-pair down-proj outputs
__device__ int   g_ptok[SLOTCAP];
__device__ float g_pw[SLOTCAP];
__device__ int   g_counts[EE];
__device__ int   g_cursor[EE];
__device__ int   g_tile_e[MAXTILES];
__device__ int   g_topk_e[TT * 2];
__device__ float g_topk_w[TT * 2];
__device__ int   g_tokpair[TT * 2];

// pack two fp32 -> f16x2 (round-to-nearest; upper = first operand)
__device__ __forceinline__ uint32_t pack_h2(float hi, float lo) {
    uint32_t r;
    asm("cvt.rn.f16x2.f32 %0, %1, %2;" : "=r"(r) : "f"(hi), "f"(lo));
    return r;
}
__device__ __forceinline__ void cvt_sts_h4(uint32_t* dst, float4 v) {
    uint2 u;
    u.x = pack_h2(v.y, v.x);    // lo half = smaller k
    u.y = pack_h2(v.w, v.z);
    *(uint2*)dst = u;
}

__device__ __forceinline__ void mma16(float* c, const uint32_t* a, uint32_t b0, uint32_t b1) {
    asm volatile(
        "mma.sync.aligned.m16n8k16.row.col.f32.f16.f16.f32 "
        "{%0,%1,%2,%3}, {%4,%5,%6,%7}, {%8,%9}, {%0,%1,%2,%3};\n"
        : "+f"(c[0]), "+f"(c[1]), "+f"(c[2]), "+f"(c[3])
        : "r"(a[0]), "r"(a[1]), "r"(a[2]), "r"(a[3]), "r"(b0), "r"(b1));
}

// ---------------------------------------------------------------------------
__global__ void k_init() {
    int i = blockIdx.x * blockDim.x + threadIdx.x;
    if (i < SLOTCAP) g_ptok[i] = -1;
    if (i < EE) g_counts[i] = 0;
}

// no-op: shifts the ncu -s/-c capture window onto a GEMM launch
__global__ void k_nop() {}

// One warp per token: logits over 8 experts, softmax, top-2.
__global__ __launch_bounds__(256) void k_gate(const float* __restrict__ x,
                                              const float* __restrict__ Wg) {
    int w = (blockIdx.x * 256 + threadIdx.x) >> 5;
    int lane = threadIdx.x & 31;
    if (w >= TT) return;
    const float* xr = x + (size_t)w * DD;
    float acc[EE];
#pragma unroll
    for (int e = 0; e < EE; e++) acc[e] = 0.f;
    for (int k = lane; k < DD; k += 32) {
        float xv = xr[k];
#pragma unroll
        for (int e = 0; e < EE; e++) acc[e] += xv * Wg[e * DD + k];
    }
#pragma unroll
    for (int e = 0; e < EE; e++) {
#pragma unroll
        for (int off = 16; off; off >>= 1)
            acc[e] += __shfl_xor_sync(0xffffffffu, acc[e], off);
    }
    if (lane == 0) {
        float mx = acc[0];
#pragma unroll
        for (int e = 1; e < EE; e++) mx = fmaxf(mx, acc[e]);
        float ex[EE], sum = 0.f;
#pragma unroll
        for (int e = 0; e < EE; e++) { ex[e] = __expf(acc[e] - mx); sum += ex[e]; }
        float inv = 1.f / sum;
        int i0 = 0; float p0 = ex[0];
#pragma unroll
        for (int e = 1; e < EE; e++) if (ex[e] > p0) { p0 = ex[e]; i0 = e; }
        int i1 = -1; float p1 = -1.f;
#pragma unroll
        for (int e = 0; e < EE; e++)
            if (e != i0 && ex[e] > p1) { p1 = ex[e]; i1 = e; }
        g_topk_e[2 * w]     = i0; g_topk_w[2 * w]     = p0 * inv;
        g_topk_e[2 * w + 1] = i1; g_topk_w[2 * w + 1] = p1 * inv;
        atomicAdd(&g_counts[i0], 1);
        atomicAdd(&g_counts[i1], 1);
    }
}

// Tiny: 128-aligned segment starts + tile->expert map.
__global__ void k_plan() {
    if (threadIdx.x == 0) {
        int start = 0, nt = 0;
        for (int e = 0; e < EE; e++) {
            g_cursor[e] = start;
            int c = g_counts[e];
            int tiles = (c + BM - 1) / BM;
            for (int i = 0; i < tiles; i++) g_tile_e[nt++] = e;
            start += tiles * BM;
        }
        for (; nt < MAXTILES; nt++) g_tile_e[nt] = -1;
    }
}

__global__ void k_scatter() {
    int t = blockIdx.x * blockDim.x + threadIdx.x;
    if (t >= TT) return;
#pragma unroll
    for (int k = 0; k < 2; k++) {
        int e = g_topk_e[2 * t + k];
        float w = g_topk_w[2 * t + k];
        int slot = atomicAdd(&g_cursor[e], 1);
        g_ptok[slot] = t;
        g_pw[slot] = w;
        g_tokpair[2 * t + k] = slot;
    }
}

// ---------------------------------------------------------------------------
// GEMM1: per m-tile (single expert), U = x W1^T, V = x W3^T over K=D,
// epilogue h = w * silu(U) * V.  128x64x32 chunks (2 x k16 mma steps),
// double-buffered smem, 8 warps (4x2) each 32x32, 2 CTAs/SM.
__global__ __launch_bounds__(256, 2) void k_up(const float* __restrict__ x,
                                               const float* __restrict__ W1,
                                               const float* __restrict__ W3) {
    int tile = blockIdx.y;
    int e = g_tile_e[tile];
    if (e < 0) return;
    int nb = blockIdx.x * BN;
    int slot0 = tile * BM;

    extern __shared__ uint32_t sm[];   // [2][STG_UP_W]: A | B1 | B3  (f16x2 words)

    int tid = threadIdx.x, lane = tid & 31, wid = tid >> 5;
    int wm = (wid & 3) * 32, wn = (wid >> 2) * 32;
    int g = lane >> 2, t4 = lane & 3;

    // staging: A = 1024 uint2 (4/thread), B1/B3 = 512 uint2 (2/thread each)
    const float* aP[4]; uint32_t aO[4];
#pragma unroll
    for (int i = 0; i < 4; i++) {
        int id = tid + 256 * i;
        int row = id >> 3, c2 = id & 7;
        int tok = g_ptok[slot0 + row]; if (tok < 0) tok = 0;
        aP[i] = x + (size_t)tok * DD + c2 * 4;
        aO[i] = row * RS + c2 * 2;
    }
    const float *b1P[2], *b3P[2]; uint32_t bO[2];
#pragma unroll
    for (int j = 0; j < 2; j++) {
        int id = tid + 256 * j;
        int row = id >> 3, c2 = id & 7;
        size_t ro = ((size_t)e * HH + nb + row) * DD + c2 * 4;
        b1P[j] = W1 + ro;
        b3P[j] = W3 + ro;
        bO[j] = row * RS + c2 * 2;
    }

    float acc_u[2][4][4], acc_v[2][4][4];
#pragma unroll
    for (int mi = 0; mi < 2; mi++)
#pragma unroll
        for (int ni = 0; ni < 4; ni++)
#pragma unroll
            for (int q = 0; q < 4; q++) { acc_u[mi][ni][q] = 0.f; acc_v[mi][ni][q] = 0.f; }

    // prologue: stage chunk 0 into buffer 0
    {
        uint32_t* A0  = sm;
        uint32_t* B10 = sm + A_WORDS;
        uint32_t* B30 = sm + A_WORDS + B_WORDS;
#pragma unroll
        for (int i = 0; i < 4; i++) cvt_sts_h4(&A0[aO[i]], *(const float4*)aP[i]);
#pragma unroll
        for (int j = 0; j < 2; j++) {
            cvt_sts_h4(&B10[bO[j]], *(const float4*)b1P[j]);
            cvt_sts_h4(&B30[bO[j]], *(const float4*)b3P[j]);
        }
    }
    __syncthreads();

#pragma unroll 1
    for (int c = 0; c < NC_UP; c++) {
        int s = c & 1;
        uint32_t* As  = sm + s * STG_UP_W;
        uint32_t* B1s = As + A_WORDS;
        uint32_t* B3s = As + A_WORDS + B_WORDS;

        // MMA phase: 2 k16-steps over the 32-wide chunk
#pragma unroll
        for (int h = 0; h < 2; h++) {
            int h8 = h * 8;
            uint32_t a[2][4];
#pragma unroll
            for (int mi = 0; mi < 2; mi++) {
                int r = wm + mi * 16 + g;
                a[mi][0] = As[r * RS + h8 + t4];
                a[mi][1] = As[(r + 8) * RS + h8 + t4];
                a[mi][2] = As[r * RS + h8 + t4 + 4];
                a[mi][3] = As[(r + 8) * RS + h8 + t4 + 4];
            }
#pragma unroll
            for (int ni = 0; ni < 4; ni++) {
                int rn = wn + ni * 8 + g;
                uint32_t bu0 = B1s[rn * RS + h8 + t4], bu1 = B1s[rn * RS + h8 + t4 + 4];
                uint32_t bv0 = B3s[rn * RS + h8 + t4], bv1 = B3s[rn * RS + h8 + t4 + 4];
#pragma unroll
                for (int mi = 0; mi < 2; mi++) {
                    mma16(acc_u[mi][ni], a[mi], bu0, bu1);
                    mma16(acc_v[mi][ni], a[mi], bv0, bv1);
                }
            }
        }

        // stage next chunk into the other buffer (gmem -> cvt -> smem);
        // latency hidden by other warps' MMA phases (2 CTAs/SM resident)
        if (c + 1 < NC_UP) {
            int kn = (c + 1) * BK;
            uint32_t* An  = sm + (s ^ 1) * STG_UP_W;
            uint32_t* B1n = An + A_WORDS;
            uint32_t* B3n = An + A_WORDS + B_WORDS;
#pragma unroll
            for (int i = 0; i < 4; i++)
                cvt_sts_h4(&An[aO[i]], *(const float4*)(aP[i] + kn));
#pragma unroll
            for (int j = 0; j < 2; j++) {
                cvt_sts_h4(&B1n[bO[j]], *(const float4*)(b1P[j] + kn));
                cvt_sts_h4(&B3n[bO[j]], *(const float4*)(b3P[j] + kn));
            }
        }
        __syncthreads();
    }

    // epilogue: h = w * silu(u) * v
#pragma unroll
    for (int mi = 0; mi < 2; mi++) {
#pragma unroll
        for (int r = 0; r < 2; r++) {
            int m = wm + mi * 16 + r * 8 + g;
            int slot = slot0 + m;
            int tok = g_ptok[slot];
            if (tok < 0) continue;
            float w = g_pw[slot];
            float* hrow = g_h + (size_t)slot * HH + nb + wn;
#pragma unroll
            for (int ni = 0; ni < 4; ni++) {
#pragma unroll
                for (int cc = 0; cc < 2; cc++) {
                    float uu = acc_u[mi][ni][r * 2 + cc];
                    float vv = acc_v[mi][ni][r * 2 + cc];
                    float si = uu / (1.f + __expf(-uu));
                    hrow[ni * 8 + t4 * 2 + cc] = w * si * vv;
                }
            }
        }
    }
}

// ---------------------------------------------------------------------------
// GEMM2: y_pair = h W2^T over K=H. Same structure, single B matrix.
__global__ __launch_bounds__(256, 2) void k_down(const float* __restrict__ W2) {
    int tile = blockIdx.y;
    int e = g_tile_e[tile];
    if (e < 0) return;
    int nb = blockIdx.x * BN;
    int slot0 = tile * BM;

    extern __shared__ uint32_t sm[];   // [2][STG_DN_W]: A | B

    int tid = threadIdx.x, lane = tid & 31, wid = tid >> 5;
    int wm = (wid & 3) * 32, wn = (wid >> 2) * 32;
    int g = lane >> 2, t4 = lane & 3;

    const float* aP[4]; uint32_t aO[4];
#pragma unroll
    for (int i = 0; i < 4; i++) {
        int id = tid + 256 * i;
        int row = id >> 3, c2 = id & 7;
        aP[i] = g_h + (size_t)(slot0 + row) * HH + c2 * 4;
        aO[i] = row * RS + c2 * 2;
    }
    const float* bP[2]; uint32_t bO[2];
#pragma unroll
    for (int j = 0; j < 2; j++) {
        int id = tid + 256 * j;
        int row = id >> 3, c2 = id & 7;
        bP[j] = W2 + ((size_t)e * DD + nb + row) * HH + c2 * 4;
        bO[j] = row * RS + c2 * 2;
    }

    float acc[2][4][4];
#pragma unroll
    for (int mi = 0; mi < 2; mi++)
#pragma unroll
        for (int ni = 0; ni < 4; ni++)
#pragma unroll
            for (int q = 0; q < 4; q++) acc[mi][ni][q] = 0.f;

    {   // prologue: chunk 0 -> buffer 0
        uint32_t* A0 = sm;
        uint32_t* B0 = sm + A_WORDS;
#pragma unroll
        for (int i = 0; i < 4; i++) cvt_sts_h4(&A0[aO[i]], *(const float4*)aP[i]);
#pragma unroll
        for (int j = 0; j < 2; j++) cvt_sts_h4(&B0[bO[j]], *(const float4*)bP[j]);
    }
    __syncthreads();

#pragma unroll 1
    for (int c = 0; c < NC_DN; c++) {
        int s = c & 1;
        uint32_t* As = sm + s * STG_DN_W;
        uint32_t* Bs = As + A_WORDS;

#pragma unroll
        for (int h = 0; h < 2; h++) {
            int h8 = h * 8;
            uint32_t a[2][4];
#pragma unroll
            for (int mi = 0; mi < 2; mi++) {
                int r = wm + mi * 16 + g;
                a[mi][0] = As[r * RS + h8 + t4];
                a[mi][1] = As[(r + 8) * RS + h8 + t4];
                a[mi][2] = As[r * RS + h8 + t4 + 4];
                a[mi][3] = As[(r + 8) * RS + h8 + t4 + 4];
            }
#pragma unroll
            for (int ni = 0; ni < 4; ni++) {
                int rn = wn + ni * 8 + g;
                uint32_t b0 = Bs[rn * RS + h8 + t4], b1 = Bs[rn * RS + h8 + t4 + 4];
#pragma unroll
                for (int mi = 0; mi < 2; mi++) mma16(acc[mi][ni], a[mi], b0, b1);
            }
        }

        if (c + 1 < NC_DN) {
            int kn = (c + 1) * BK;
            uint32_t* An = sm + (s ^ 1) * STG_DN_W;
            uint32_t* Bn = An + A_WORDS;
#pragma unroll
            for (int i = 0; i < 4; i++)
                cvt_sts_h4(&An[aO[i]], *(const float4*)(aP[i] + kn));
#pragma unroll
            for (int j = 0; j < 2; j++)
                cvt_sts_h4(&Bn[bO[j]], *(const float4*)(bP[j] + kn));
        }
        __syncthreads();
    }

#pragma unroll
    for (int mi = 0; mi < 2; mi++) {
#pragma unroll
        for (int r = 0; r < 2; r++) {
            int m = wm + mi * 16 + r * 8 + g;
            int slot = slot0 + m;
            if (g_ptok[slot] < 0) continue;
            float* yrow = g_yp + (size_t)slot * DD + nb + wn;
#pragma unroll
            for (int ni = 0; ni < 4; ni++) {
#pragma unroll
                for (int cc = 0; cc < 2; cc++)
                    yrow[ni * 8 + t4 * 2 + cc] = acc[mi][ni][r * 2 + cc];
            }
        }
    }
}

// out[t] = x[t] + y_pair[p0(t)] + y_pair[p1(t)]  (deterministic gather)
__global__ __launch_bounds__(512) void k_combine(const float* __restrict__ x,
                                                 float* __restrict__ out) {
    int t = blockIdx.x;
    int d = threadIdx.x * 4;
    int s0 = g_tokpair[2 * t], s1 = g_tokpair[2 * t + 1];
    float4 xv = *(const float4*)(x + (size_t)t * DD + d);
    float4 a = *(const float4*)(g_yp + (size_t)s0 * DD + d);
    float4 b = *(const float4*)(g_yp + (size_t)s1 * DD + d);
    float4 o;
    o.x = xv.x + a.x + b.x;
    o.y = xv.y + a.y + b.y;
    o.z = xv.z + a.z + b.z;
    o.w = xv.w + a.w + b.w;
    *(float4*)(out + (size_t)t * DD + d) = o;
}

// ---------------------------------------------------------------------------
extern "C" void kernel_launch(void* const* d_in, const int* in_sizes, int n_in,
                              void* d_out, int out_size) {
    const float* x  = (const float*)d_in[0];
    const float* Wg = (const float*)d_in[1];
    const float* W1 = (const float*)d_in[2];
    const float* W3 = (const float*)d_in[3];
    const float* W2 = (const float*)d_in[4];
    float* out = (float*)d_out;

    k_init<<<(SLOTCAP + 255) / 256, 256>>>();
    k_gate<<<(TT * 32 + 255) / 256, 256>>>(x, Wg);
    k_plan<<<1, 32>>>();
    k_scatter<<<(TT + 255) / 256, 256>>>();
    k_nop<<<1, 32>>>();   // shifts ncu -s5 -c1 capture onto a GEMM launch
    k_up<<<dim3(HH / BN, MAXTILES), 256, SMEM_UP_B>>>(x, W1, W3);
    k_down<<<dim3(DD / BN, MAXTILES), 256, SMEM_DN_B>>>(W2);
    k_combine<<<TT, DD / 4>>>(x, out);
}